// round 14
// baseline (speedup 1.0000x reference)
#include <cuda_runtime.h>
#include <cuda_fp16.h>
#include <cstdint>

// ============================================================
// Problem sizes
// ============================================================
#define BATCH   4096
#define IN_SZ   2048
#define HID     4096
#define NCLS    1000
#define NCLSP   1024   // padded N for layer 3

// ============================================================
// Device scratch (allocation-free rule: __device__ globals)
// ============================================================
__device__ __half g_X  [(size_t)BATCH * IN_SZ];
__device__ __half g_W1 [(size_t)HID   * IN_SZ];   // [N=HID, K=IN_SZ] K-major
__device__ __half g_W2 [(size_t)HID   * HID];
__device__ __half g_W3 [(size_t)NCLSP * HID];
__device__ __half g_H1 [(size_t)BATCH * HID];
__device__ __half g_H2 [(size_t)BATCH * HID];

// ============================================================
// Baseline-target PTX helpers (NO a-suffix features)
// ============================================================
__device__ __forceinline__ uint32_t smem_u32(const void* p) {
    uint32_t a;
    asm("{ .reg .u64 t; cvta.to.shared.u64 t, %1; cvt.u32.u64 %0, t; }"
        : "=r"(a) : "l"(p));
    return a;
}

#define CP_ASYNC16(dst, src) \
    asm volatile("cp.async.cg.shared.global [%0], [%1], 16;" \
        :: "r"(dst), "l"(src) : "memory")
#define CP_COMMIT() asm volatile("cp.async.commit_group;" ::: "memory")
#define CP_WAIT(n)  asm volatile("cp.async.wait_group %0;" :: "n"(n) : "memory")

#define LDSM4(r0, r1, r2, r3, addr) \
    asm volatile("ldmatrix.sync.aligned.m8n8.x4.shared.b16 {%0,%1,%2,%3}, [%4];" \
        : "=r"(r0), "=r"(r1), "=r"(r2), "=r"(r3) : "r"(addr))

#define MMA16816(d, a, b) \
    asm volatile("mma.sync.aligned.m16n8k16.row.col.f32.f16.f16.f32 " \
        "{%0,%1,%2,%3}, {%4,%5,%6,%7}, {%8,%9}, {%0,%1,%2,%3};" \
        : "+f"((d)[0]), "+f"((d)[1]), "+f"((d)[2]), "+f"((d)[3]) \
        : "r"((a)[0]), "r"((a)[1]), "r"((a)[2]), "r"((a)[3]), \
          "r"((b)[0]), "r"((b)[1]))

// ============================================================
// Pre-pass 1: elementwise convert fp32 -> fp16
// ============================================================
__global__ void __launch_bounds__(256)
convert_kernel(const float* __restrict__ in, __half* __restrict__ o, int n4)
{
    int i = blockIdx.x * 256 + threadIdx.x;
    if (i >= n4) return;
    float4 v = reinterpret_cast<const float4*>(in)[i];
    __half2* o2 = reinterpret_cast<__half2*>(o);
    o2[i * 2 + 0] = __half2(__float2half_rn(v.x), __float2half_rn(v.y));
    o2[i * 2 + 1] = __half2(__float2half_rn(v.z), __float2half_rn(v.w));
}

// ============================================================
// Pre-pass 2: transpose [K,N] fp32 -> [Npad,K] fp16 (zero-pad n>=N)
// ============================================================
__global__ void __launch_bounds__(256)
transpose_h_kernel(const float* __restrict__ w, __half* __restrict__ oh,
                   int K, int N, int Npad)
{
    __shared__ float t[32][33];
    int n0 = blockIdx.x * 32;
    int k0 = blockIdx.y * 32;
    #pragma unroll
    for (int r = threadIdx.y; r < 32; r += 8) {
        int n = n0 + threadIdx.x;
        float v = 0.0f;
        if (n < N) v = w[(size_t)(k0 + r) * N + n];
        t[r][threadIdx.x] = v;
    }
    __syncthreads();
    #pragma unroll
    for (int r = threadIdx.y; r < 32; r += 8) {
        int n = n0 + r;
        int k = k0 + threadIdx.x;
        oh[(size_t)n * K + k] = __float2half_rn(t[threadIdx.x][r]);
    }
}

// ============================================================
// GEMM: C[M,N] = op(A @ B^T + bias), pure fp16, fp32 accumulate
//   A: [M,K] K-major fp16;  B: [N,K] K-major fp16
// CTA tile 128x256, K-chunk 128, 2-stage cp.async pipeline
// (wait -> sync -> issue next loads into freed buffer -> compute: full overlap).
// 512 threads = 16 warps in 2(M) x 8(N); warp tile 64x32.
// Regs: acc 64 + frags 24 (single-term fp16) -> fits 128-reg cap, no spill.
// SMEM rows padded to 272 B (128 fp16 data + 16 pad):
//   r*272 mod 128 = 16r -> 8 distinct 16B slots per 8-row ldmatrix phase.
// ============================================================
#define ROWB        272
#define KC          128
#define TILE_M      128
#define TILE_N      256
#define OFF_A       0
#define OFF_B       (TILE_M * ROWB)                    // 34816
#define STAGE_BYTES ((TILE_M + TILE_N) * ROWB)         // 104448
#define NSTAGE      2
#define SMEM_TOTAL  (NSTAGE * STAGE_BYTES)             // 208896

__global__ void __launch_bounds__(512, 1)
gemm_h_kernel(const __half* __restrict__ A, const __half* __restrict__ B,
              const float* __restrict__ bias,
              float* __restrict__ Cf, __half* __restrict__ Ch,
              int M, int N, int K, int Nreal, int do_relu, int h_out)
{
    extern __shared__ char smem[];
    const uint32_t sbase = smem_u32(smem);
    const int tid  = threadIdx.x;
    const int wid  = tid >> 5;
    const int lane = tid & 31;
    const int wm   = wid >> 3;   // 0..1 (M)
    const int wn   = wid & 7;    // 0..7 (N)

    // ---- block swizzle for L2 locality ----
    const int tiles_n = N / TILE_N;
    const int tiles_m = M / TILE_M;
    const int G = 8;
    const int bpg = G * tiles_n;
    const int group = blockIdx.x / bpg;
    const int rem = blockIdx.x - group * bpg;
    int gsz = tiles_m - group * G; if (gsz > G) gsz = G;
    const int tm = group * G + rem % gsz;
    const int tn = rem / gsz;
    const int m0 = tm * TILE_M;
    const int n0 = tn * TILE_N;

    // loader mapping:
    //  A: 128 rows x 16 cols of 16B; thread: row tid>>2, cols (tid&3)+4j, j=0..3
    //  B: 256 rows x 16 cols of 16B; thread: row tid>>1, cols (tid&1)*8+j, j=0..7
    const int a_r = tid >> 2;
    const int a_c = tid & 3;
    const int b_r = tid >> 1;
    const int b_c = (tid & 1) * 8;

    // ldmatrix per-lane addressing
    const uint32_t lrow16 = (uint32_t)(lane & 15) * ROWB + (uint32_t)(lane >> 4) * 16;
    const uint32_t aFragOff = (uint32_t)(wm * 64) * ROWB + lrow16;
    const uint32_t bFragOff = (uint32_t)(wn * 32) * ROWB + lrow16;

    float acc[4][4][4];
    #pragma unroll
    for (int mt = 0; mt < 4; ++mt)
        #pragma unroll
        for (int nt = 0; nt < 4; ++nt)
            #pragma unroll
            for (int e = 0; e < 4; ++e) acc[mt][nt][e] = 0.0f;

    const int nch = K / KC;

    auto load_stage = [&](int chunk, int buf) {
        const int kb = chunk * KC;
        const uint32_t sg = sbase + (uint32_t)buf * STAGE_BYTES;
        const uint32_t sa = sg + OFF_A + (uint32_t)a_r * ROWB + (uint32_t)a_c * 16;
        const size_t gA = (size_t)(m0 + a_r) * K + kb + a_c * 8;
        #pragma unroll
        for (int j = 0; j < 4; ++j)
            CP_ASYNC16(sa + j * 64, A + gA + j * 32);
        const uint32_t sb = sg + OFF_B + (uint32_t)b_r * ROWB + (uint32_t)b_c * 16;
        const size_t gB = (size_t)(n0 + b_r) * K + kb + b_c * 8;
        #pragma unroll
        for (int j = 0; j < 8; ++j)
            CP_ASYNC16(sb + j * 16, B + gB + j * 8);
    };

    load_stage(0, 0); CP_COMMIT();

    int buf = 0;
    for (int c = 0; c < nch; ++c) {
        CP_WAIT(0);
        __syncthreads();
        // issue next stage into the buffer freed by last iteration's compute
        if (c + 1 < nch) { load_stage(c + 1, buf ^ 1); CP_COMMIT(); }

        const uint32_t sg = sbase + (uint32_t)buf * STAGE_BYTES;
        #pragma unroll
        for (int ks = 0; ks < 8; ++ks) {
            const uint32_t ko = (uint32_t)ks * 32;  // K16 slice = 32 bytes
            uint32_t ah[4][4], bh[4][2];
            #pragma unroll
            for (int mt = 0; mt < 4; ++mt) {
                uint32_t a = sg + OFF_A + aFragOff + (uint32_t)mt * (16 * ROWB) + ko;
                LDSM4(ah[mt][0], ah[mt][1], ah[mt][2], ah[mt][3], a);
            }
            #pragma unroll
            for (int ntp = 0; ntp < 2; ++ntp) {
                uint32_t b = sg + OFF_B + bFragOff + (uint32_t)ntp * (16 * ROWB) + ko;
                uint32_t r0, r1, r2, r3;
                LDSM4(r0, r1, r2, r3, b);
                bh[2 * ntp][0] = r0; bh[2 * ntp][1] = r2;
                bh[2 * ntp + 1][0] = r1; bh[2 * ntp + 1][1] = r3;
            }
            #pragma unroll
            for (int mt = 0; mt < 4; ++mt)
                #pragma unroll
                for (int nt = 0; nt < 4; ++nt)
                    MMA16816(acc[mt][nt], ah[mt], bh[nt]);
        }
        buf ^= 1;
    }

    // ---- epilogue: bias (+relu) fused; fp16 or fp32 out ----
    const int mrow = lane >> 2;
    const int ncol = (lane & 3) * 2;
    #pragma unroll
    for (int mt = 0; mt < 4; ++mt) {
        #pragma unroll
        for (int nt = 0; nt < 4; ++nt) {
            const int n = n0 + wn * 32 + nt * 8 + ncol;
            float bx = 0.0f, by = 0.0f;
            if (h_out) {
                float2 bv = *reinterpret_cast<const float2*>(bias + n);
                bx = bv.x; by = bv.y;
            } else {
                if (n     < Nreal) bx = bias[n];
                if (n + 1 < Nreal) by = bias[n + 1];
            }
            #pragma unroll
            for (int half = 0; half < 2; ++half) {
                const int m = m0 + wm * 64 + mt * 16 + mrow + half * 8;
                float v0 = acc[mt][nt][half * 2 + 0] + bx;
                float v1 = acc[mt][nt][half * 2 + 1] + by;
                if (do_relu) {
                    v0 = v0 > 0.0f ? v0 : 0.0f;
                    v1 = v1 > 0.0f ? v1 : 0.0f;
                }
                if (h_out) {
                    *reinterpret_cast<__half2*>(Ch + (size_t)m * N + n) =
                        __half2(__float2half_rn(v0), __float2half_rn(v1));
                } else {
                    if (n     < Nreal) Cf[(size_t)m * Nreal + n]     = v0;
                    if (n + 1 < Nreal) Cf[(size_t)m * Nreal + n + 1] = v1;
                }
            }
        }
    }
}

// ============================================================
// Launch
// ============================================================
extern "C" void kernel_launch(void* const* d_in, const int* in_sizes, int n_in,
                              void* d_out, int out_size)
{
    const float* x  = (const float*)d_in[0];
    const float* w1 = (const float*)d_in[1];
    const float* b1 = (const float*)d_in[2];
    const float* w2 = (const float*)d_in[3];
    const float* b2 = (const float*)d_in[4];
    const float* w3 = (const float*)d_in[5];
    const float* b3 = (const float*)d_in[6];
    float* out = (float*)d_out;

    void *pX, *pW1, *pW2, *pW3, *pH1, *pH2;
    cudaGetSymbolAddress(&pX,  g_X);
    cudaGetSymbolAddress(&pW1, g_W1);
    cudaGetSymbolAddress(&pW2, g_W2);
    cudaGetSymbolAddress(&pW3, g_W3);
    cudaGetSymbolAddress(&pH1, g_H1);
    cudaGetSymbolAddress(&pH2, g_H2);

    cudaFuncSetAttribute(gemm_h_kernel,
                         cudaFuncAttributeMaxDynamicSharedMemorySize, SMEM_TOTAL);

    // --- pre-pass: convert x; transpose weights to fp16 ---
    {
        int n4 = (BATCH * IN_SZ) / 4;
        convert_kernel<<<(n4 + 255) / 256, 256>>>(x, (__half*)pX, n4);
    }
    transpose_h_kernel<<<dim3(HID / 32, IN_SZ / 32), dim3(32, 8)>>>(
        w1, (__half*)pW1, IN_SZ, HID, HID);
    transpose_h_kernel<<<dim3(HID / 32, HID / 32), dim3(32, 8)>>>(
        w2, (__half*)pW2, HID, HID, HID);
    transpose_h_kernel<<<dim3(NCLSP / 32, HID / 32), dim3(32, 8)>>>(
        w3, (__half*)pW3, HID, NCLS, NCLSP);

    // --- layer 1: h1 = relu(x @ w1 + b1), fp16 out ---
    gemm_h_kernel<<<(BATCH / TILE_M) * (HID / TILE_N), 512, SMEM_TOTAL>>>(
        (const __half*)pX, (const __half*)pW1,
        b1, nullptr, (__half*)pH1,
        BATCH, HID, IN_SZ, HID, 1, 1);

    // --- layer 2: h2 = relu(h1 @ w2 + b2), fp16 out ---
    gemm_h_kernel<<<(BATCH / TILE_M) * (HID / TILE_N), 512, SMEM_TOTAL>>>(
        (const __half*)pH1, (const __half*)pW2,
        b2, nullptr, (__half*)pH2,
        BATCH, HID, HID, HID, 1, 1);

    // --- layer 3: out = h2 @ w3 + b3, fp32 out (N padded 1024 -> 1000) ---
    gemm_h_kernel<<<(BATCH / TILE_M) * (NCLSP / TILE_N), 512, SMEM_TOTAL>>>(
        (const __half*)pH2, (const __half*)pW3,
        b3, out, nullptr,
        BATCH, NCLSP, HID, NCLS, 0, 0);
}

// round 15
// speedup vs baseline: 1.2554x; 1.2554x over previous
#include <cuda_runtime.h>
#include <cuda_fp16.h>
#include <cstdint>

// ============================================================
// Problem sizes
// ============================================================
#define BATCH   4096
#define IN_SZ   2048
#define HID     4096
#define NCLS    1000
#define NCLSP   1024   // padded N for layer 3

// ============================================================
// Device scratch (allocation-free rule: __device__ globals)
// ============================================================
__device__ __half g_X  [(size_t)BATCH * IN_SZ];
__device__ __half g_W1 [(size_t)HID   * IN_SZ];   // [N=HID, K=IN_SZ] K-major
__device__ __half g_W2 [(size_t)HID   * HID];
__device__ __half g_W3 [(size_t)NCLSP * HID];
__device__ __half g_H1 [(size_t)BATCH * HID];
__device__ __half g_H2 [(size_t)BATCH * HID];

// ============================================================
// Baseline-target PTX helpers (NO a-suffix features)
// ============================================================
__device__ __forceinline__ uint32_t smem_u32(const void* p) {
    uint32_t a;
    asm("{ .reg .u64 t; cvta.to.shared.u64 t, %1; cvt.u32.u64 %0, t; }"
        : "=r"(a) : "l"(p));
    return a;
}

#define CP_ASYNC16(dst, src) \
    asm volatile("cp.async.cg.shared.global [%0], [%1], 16;" \
        :: "r"(dst), "l"(src) : "memory")
#define CP_COMMIT() asm volatile("cp.async.commit_group;" ::: "memory")
#define CP_WAIT(n)  asm volatile("cp.async.wait_group %0;" :: "n"(n) : "memory")

#define LDSM4(r0, r1, r2, r3, addr) \
    asm volatile("ldmatrix.sync.aligned.m8n8.x4.shared.b16 {%0,%1,%2,%3}, [%4];" \
        : "=r"(r0), "=r"(r1), "=r"(r2), "=r"(r3) : "r"(addr))

#define MMA16816(d, a, b) \
    asm volatile("mma.sync.aligned.m16n8k16.row.col.f32.f16.f16.f32 " \
        "{%0,%1,%2,%3}, {%4,%5,%6,%7}, {%8,%9}, {%0,%1,%2,%3};" \
        : "+f"((d)[0]), "+f"((d)[1]), "+f"((d)[2]), "+f"((d)[3]) \
        : "r"((a)[0]), "r"((a)[1]), "r"((a)[2]), "r"((a)[3]), \
          "r"((b)[0]), "r"((b)[1]))

// ============================================================
// Pre-pass 1: elementwise convert fp32 -> fp16
// ============================================================
__global__ void __launch_bounds__(256)
convert_kernel(const float* __restrict__ in, __half* __restrict__ o, int n4)
{
    int i = blockIdx.x * 256 + threadIdx.x;
    if (i >= n4) return;
    float4 v = reinterpret_cast<const float4*>(in)[i];
    __half2* o2 = reinterpret_cast<__half2*>(o);
    o2[i * 2 + 0] = __half2(__float2half_rn(v.x), __float2half_rn(v.y));
    o2[i * 2 + 1] = __half2(__float2half_rn(v.z), __float2half_rn(v.w));
}

// ============================================================
// Pre-pass 2: transpose [K,N] fp32 -> [Npad,K] fp16 (zero-pad n>=N)
// ============================================================
__global__ void __launch_bounds__(256)
transpose_h_kernel(const float* __restrict__ w, __half* __restrict__ oh,
                   int K, int N, int Npad)
{
    __shared__ float t[32][33];
    int n0 = blockIdx.x * 32;
    int k0 = blockIdx.y * 32;
    #pragma unroll
    for (int r = threadIdx.y; r < 32; r += 8) {
        int n = n0 + threadIdx.x;
        float v = 0.0f;
        if (n < N) v = w[(size_t)(k0 + r) * N + n];
        t[r][threadIdx.x] = v;
    }
    __syncthreads();
    #pragma unroll
    for (int r = threadIdx.y; r < 32; r += 8) {
        int n = n0 + r;
        int k = k0 + threadIdx.x;
        oh[(size_t)n * K + k] = __float2half_rn(t[threadIdx.x][r]);
    }
}

// ============================================================
// GEMM: C[M,N] = op(A @ B^T + bias), pure fp16, fp32 accumulate
//   A: [M,K] K-major fp16;  B: [N,K] K-major fp16
// CTA tile 128x128, K-chunk 128, 3-stage cp.async pipeline.
// 512 threads = 16 warps in 4(M) x 4(N); warp tile 32x32 (acc=32 regs, no spill).
// Fragment loads software-pipelined one K16 step ahead (double-buffered
// frag regs) so LDSM latency hides under the 8 MMAs of the previous step.
// SMEM rows padded to 272 B (128 fp16 data + 16 pad):
//   r*272 mod 128 = 16r -> 8 distinct 16B slots per 8-row ldmatrix phase.
// ============================================================
#define ROWB        272
#define KC          128
#define OFF_A       0
#define OFF_B       (128 * ROWB)            // 34816
#define STAGE_BYTES (2 * 128 * ROWB)        // 69632
#define NSTAGE      3
#define SMEM_TOTAL  (NSTAGE * STAGE_BYTES)  // 208896

__global__ void __launch_bounds__(512, 1)
gemm_h_kernel(const __half* __restrict__ A, const __half* __restrict__ B,
              const float* __restrict__ bias,
              float* __restrict__ Cf, __half* __restrict__ Ch,
              int M, int N, int K, int Nreal, int do_relu, int h_out)
{
    extern __shared__ char smem[];
    const uint32_t sbase = smem_u32(smem);
    const int tid  = threadIdx.x;
    const int wid  = tid >> 5;
    const int lane = tid & 31;
    const int wm   = wid >> 2;   // 0..3
    const int wn   = wid & 3;    // 0..3

    // ---- block swizzle for L2 locality ----
    const int tiles_n = N >> 7;
    const int tiles_m = M >> 7;
    const int G = 8;
    const int bpg = G * tiles_n;
    const int group = blockIdx.x / bpg;
    const int rem = blockIdx.x - group * bpg;
    int gsz = tiles_m - group * G; if (gsz > G) gsz = G;
    const int tm = group * G + rem % gsz;
    const int tn = rem / gsz;
    const int m0 = tm << 7;
    const int n0 = tn << 7;

    // loader mapping: per array 128 rows x 16 cols of 16B.
    const int ld_r = tid >> 2;    // 0..127
    const int ld_c = tid & 3;     // 0..3

    // ldmatrix per-lane addressing
    const uint32_t lrow16 = (uint32_t)(lane & 15) * ROWB + (uint32_t)(lane >> 4) * 16;
    const uint32_t aFragOff = (uint32_t)(wm * 32) * ROWB + lrow16 + OFF_A;
    const uint32_t bFragOff = (uint32_t)(wn * 32) * ROWB + lrow16 + OFF_B;

    float acc[2][4][4];
    #pragma unroll
    for (int mt = 0; mt < 2; ++mt)
        #pragma unroll
        for (int nt = 0; nt < 4; ++nt)
            #pragma unroll
            for (int e = 0; e < 4; ++e) acc[mt][nt][e] = 0.0f;

    const int nch = K / KC;

    auto load_stage = [&](int chunk, int buf) {
        const int kb = chunk * KC;
        const uint32_t s0 = sbase + (uint32_t)buf * STAGE_BYTES
                          + (uint32_t)ld_r * ROWB + (uint32_t)ld_c * 16;
        const size_t gA = (size_t)(m0 + ld_r) * K + kb + ld_c * 8;
        const size_t gB = (size_t)(n0 + ld_r) * K + kb + ld_c * 8;
        #pragma unroll
        for (int j = 0; j < 4; ++j) {
            CP_ASYNC16(s0 + OFF_A + j * 64, A + gA + j * 32);
            CP_ASYNC16(s0 + OFF_B + j * 64, B + gB + j * 32);
        }
    };

    // prologue: fill NSTAGE-1 stages
    load_stage(0, 0); CP_COMMIT();
    load_stage(1, 1); CP_COMMIT();

    // double-buffered fragments
    uint32_t ah[2][2][4], bh[2][4][2];

    auto load_frags = [&](uint32_t sg, int ks, int fb) {
        const uint32_t ko = (uint32_t)ks * 32;
        #pragma unroll
        for (int mt = 0; mt < 2; ++mt) {
            uint32_t a = sg + aFragOff + (uint32_t)mt * (16 * ROWB) + ko;
            LDSM4(ah[fb][mt][0], ah[fb][mt][1], ah[fb][mt][2], ah[fb][mt][3], a);
        }
        #pragma unroll
        for (int ntp = 0; ntp < 2; ++ntp) {
            uint32_t b = sg + bFragOff + (uint32_t)ntp * (16 * ROWB) + ko;
            uint32_t r0, r1, r2, r3;
            LDSM4(r0, r1, r2, r3, b);
            bh[fb][2 * ntp][0] = r0; bh[fb][2 * ntp][1] = r2;
            bh[fb][2 * ntp + 1][0] = r1; bh[fb][2 * ntp + 1][1] = r3;
        }
    };

    int buf = 0;
    for (int c = 0; c < nch; ++c) {
        if (c >= nch - (NSTAGE - 1)) { CP_WAIT(0); }
        else                         { CP_WAIT(NSTAGE - 2); }
        __syncthreads();

        const uint32_t sg = sbase + (uint32_t)buf * STAGE_BYTES;

        // issue next global stage first (latency-longest)
        const int nx = c + NSTAGE - 1;
        if (nx < nch) { load_stage(nx, nx % NSTAGE); CP_COMMIT(); }

        // fragment prologue: load ks=0 into fb=0
        load_frags(sg, 0, 0);

        #pragma unroll
        for (int ks = 0; ks < 8; ++ks) {
            const int fb = ks & 1;
            if (ks + 1 < 8) load_frags(sg, ks + 1, fb ^ 1);
            #pragma unroll
            for (int mt = 0; mt < 2; ++mt)
                #pragma unroll
                for (int nt = 0; nt < 4; ++nt)
                    MMA16816(acc[mt][nt], ah[fb][mt], bh[fb][nt]);
        }

        buf = (buf + 1 == NSTAGE) ? 0 : buf + 1;
    }

    // ---- epilogue: bias (+relu) fused; fp16 or fp32 out ----
    const int mrow = lane >> 2;
    const int ncol = (lane & 3) * 2;
    #pragma unroll
    for (int mt = 0; mt < 2; ++mt) {
        #pragma unroll
        for (int nt = 0; nt < 4; ++nt) {
            const int n = n0 + wn * 32 + nt * 8 + ncol;
            float bx = 0.0f, by = 0.0f;
            if (h_out) {
                float2 bv = *reinterpret_cast<const float2*>(bias + n);
                bx = bv.x; by = bv.y;
            } else {
                if (n     < Nreal) bx = bias[n];
                if (n + 1 < Nreal) by = bias[n + 1];
            }
            #pragma unroll
            for (int half = 0; half < 2; ++half) {
                const int m = m0 + wm * 32 + mt * 16 + mrow + half * 8;
                float v0 = acc[mt][nt][half * 2 + 0] + bx;
                float v1 = acc[mt][nt][half * 2 + 1] + by;
                if (do_relu) {
                    v0 = v0 > 0.0f ? v0 : 0.0f;
                    v1 = v1 > 0.0f ? v1 : 0.0f;
                }
                if (h_out) {
                    *reinterpret_cast<__half2*>(Ch + (size_t)m * N + n) =
                        __half2(__float2half_rn(v0), __float2half_rn(v1));
                } else {
                    if (n     < Nreal) Cf[(size_t)m * Nreal + n]     = v0;
                    if (n + 1 < Nreal) Cf[(size_t)m * Nreal + n + 1] = v1;
                }
            }
        }
    }
}

// ============================================================
// Launch
// ============================================================
extern "C" void kernel_launch(void* const* d_in, const int* in_sizes, int n_in,
                              void* d_out, int out_size)
{
    const float* x  = (const float*)d_in[0];
    const float* w1 = (const float*)d_in[1];
    const float* b1 = (const float*)d_in[2];
    const float* w2 = (const float*)d_in[3];
    const float* b2 = (const float*)d_in[4];
    const float* w3 = (const float*)d_in[5];
    const float* b3 = (const float*)d_in[6];
    float* out = (float*)d_out;

    void *pX, *pW1, *pW2, *pW3, *pH1, *pH2;
    cudaGetSymbolAddress(&pX,  g_X);
    cudaGetSymbolAddress(&pW1, g_W1);
    cudaGetSymbolAddress(&pW2, g_W2);
    cudaGetSymbolAddress(&pW3, g_W3);
    cudaGetSymbolAddress(&pH1, g_H1);
    cudaGetSymbolAddress(&pH2, g_H2);

    cudaFuncSetAttribute(gemm_h_kernel,
                         cudaFuncAttributeMaxDynamicSharedMemorySize, SMEM_TOTAL);

    // --- pre-pass: convert x; transpose weights to fp16 ---
    {
        int n4 = (BATCH * IN_SZ) / 4;
        convert_kernel<<<(n4 + 255) / 256, 256>>>(x, (__half*)pX, n4);
    }
    transpose_h_kernel<<<dim3(HID / 32, IN_SZ / 32), dim3(32, 8)>>>(
        w1, (__half*)pW1, IN_SZ, HID, HID);
    transpose_h_kernel<<<dim3(HID / 32, HID / 32), dim3(32, 8)>>>(
        w2, (__half*)pW2, HID, HID, HID);
    transpose_h_kernel<<<dim3(NCLSP / 32, HID / 32), dim3(32, 8)>>>(
        w3, (__half*)pW3, HID, NCLS, NCLSP);

    // --- layer 1: h1 = relu(x @ w1 + b1), fp16 out ---
    gemm_h_kernel<<<(BATCH / 128) * (HID / 128), 512, SMEM_TOTAL>>>(
        (const __half*)pX, (const __half*)pW1,
        b1, nullptr, (__half*)pH1,
        BATCH, HID, IN_SZ, HID, 1, 1);

    // --- layer 2: h2 = relu(h1 @ w2 + b2), fp16 out ---
    gemm_h_kernel<<<(BATCH / 128) * (HID / 128), 512, SMEM_TOTAL>>>(
        (const __half*)pH1, (const __half*)pW2,
        b2, nullptr, (__half*)pH2,
        BATCH, HID, HID, HID, 1, 1);

    // --- layer 3: out = h2 @ w3 + b3, fp32 out (N padded 1024 -> 1000) ---
    gemm_h_kernel<<<(BATCH / 128) * (NCLSP / 128), 512, SMEM_TOTAL>>>(
        (const __half*)pH2, (const __half*)pW3,
        b3, out, nullptr,
        BATCH, NCLSP, HID, NCLS, 0, 0);
}